// round 1
// baseline (speedup 1.0000x reference)
#include <cuda_runtime.h>
#include <cstdint>
#include <cfloat>

// Problem shapes (fixed by setup_inputs)
#define BB   16
#define NN   1024
#define DD   1024
#define PP   256
#define KNN  16
#define MM   (BB * NN)     // 16384

// ---------------- scratch (device globals; no allocation allowed) ----------
__device__ float g_feats_low[MM * PP];        // 16 MB
__device__ float g_Wcomb[PP * 2 * PP];        // 0.5 MB : [f][0:256]=W1-W2, [f][256:512]=W2
__device__ float g_AB[(size_t)MM * 2 * PP];   // 32 MB : [m][0:256]=A', [m][256:512]=Bv
__device__ int   g_idx[MM * KNN];             // 1 MB
__device__ float g_local[MM * PP];            // 16 MB
__device__ float g_s[PP];
__device__ float g_t[PP];

// ---------------- prep: Wcomb + folded BN affine ---------------------------
__global__ void prep_kernel(const float* __restrict__ W_edge,
                            const float* __restrict__ b_edge,
                            const float* __restrict__ gamma,
                            const float* __restrict__ beta,
                            const float* __restrict__ mean,
                            const float* __restrict__ var)
{
    int tid = blockIdx.x * blockDim.x + threadIdx.x;   // 0 .. 65535
    if (tid < PP * PP) {
        int f = tid >> 8;          // feats_low dim 0..255
        int p = tid & 255;         // output dim
        float w1 = W_edge[f * PP + p];
        float w2 = W_edge[(f + PP) * PP + p];
        g_Wcomb[f * (2 * PP) + p]       = w1 - w2;
        g_Wcomb[f * (2 * PP) + PP + p]  = w2;
    }
    if (tid < PP) {
        float rs = rsqrtf(var[tid] + 1e-5f);
        float sv = gamma[tid] * rs;
        g_s[tid] = sv;
        g_t[tid] = beta[tid] - mean[tid] * sv + sv * b_edge[tid];
    }
}

// ---------------- KNN: top-16 smallest d2 per (b,n) ------------------------
__global__ __launch_bounds__(64) void knn_kernel(const float* __restrict__ pts)
{
    const int b = blockIdx.y;
    const int n = blockIdx.x * 64 + threadIdx.x;

    __shared__ float sx[NN], sy[NN], sz[NN], ssq[NN];
    for (int m = threadIdx.x; m < NN; m += 64) {
        float x = pts[((size_t)b * NN + m) * 3 + 0];
        float y = pts[((size_t)b * NN + m) * 3 + 1];
        float z = pts[((size_t)b * NN + m) * 3 + 2];
        sx[m] = x; sy[m] = y; sz[m] = z;
        ssq[m] = x * x + y * y + z * z;
    }
    __syncthreads();

    const float px = sx[n], py = sy[n], pz = sz[n], psq = ssq[n];

    float bd[KNN];
    int   bi[KNN];
#pragma unroll
    for (int j = 0; j < KNN; ++j) { bd[j] = FLT_MAX; bi[j] = 0; }

    for (int m = 0; m < NN; ++m) {
        float dot = px * sx[m] + py * sy[m] + pz * sz[m];
        float d = psq + ssq[m] - 2.0f * dot;
        if (d < bd[KNN - 1]) {
            float dc = d; int ic = m;
#pragma unroll
            for (int j = 0; j < KNN; ++j) {
                if (dc < bd[j]) {
                    float td = bd[j]; bd[j] = dc; dc = td;
                    int   ti = bi[j]; bi[j] = ic; ic = ti;
                }
            }
        }
    }

    int base = ((size_t)b * NN + n) * KNN;
#pragma unroll
    for (int j = 0; j < KNN; ++j) g_idx[base + j] = bi[j];
}

// ---------------- edge gather + BN affine + relu + max over K --------------
__global__ __launch_bounds__(256) void edge_max_kernel()
{
    const int bn = blockIdx.x;          // 0 .. 16383
    const int p  = threadIdx.x;         // 0 .. 255
    const int b  = bn >> 10;

    __shared__ int sidx[KNN];
    if (p < KNN) sidx[p] = g_idx[bn * KNN + p];
    __syncthreads();

    const float a  = g_AB[(size_t)bn * 512 + p];
    const float sp = g_s[p];
    const float tp = g_t[p];

    float acc = 0.0f;                   // max over relu(..) is >= 0
#pragma unroll
    for (int k = 0; k < KNN; ++k) {
        float v = g_AB[(size_t)((b << 10) + sidx[k]) * 512 + PP + p];
        float h = fmaf(sp, a + v, tp);
        acc = fmaxf(acc, h);
    }
    g_local[(size_t)bn * PP + p] = acc;
}

// ---------------- 128x128x8 fp32 SGEMM, 256 threads, 8x8 microtile ---------
// EPI: 0 = plain store, 1 = relu(x + bias[col]), 2 = x + bias[col] + res[row,col]
template <int EPI>
__global__ __launch_bounds__(256) void sgemm128(
    const float* __restrict__ A, const float* __restrict__ Bm,
    float* __restrict__ C, int M, int N, int K,
    const float* __restrict__ bias, const float* __restrict__ res)
{
    const int tid = threadIdx.x;
    const int bm = blockIdx.y, bn = blockIdx.x;

    __shared__ float As[8][128];
    __shared__ float Bs[8][128];

    float acc[8][8] = {};

    const int ty = tid >> 4, tx = tid & 15;
    const int aRow = tid >> 1,  aCol = (tid & 1) * 4;
    const int bRow = tid >> 5,  bCol = (tid & 31) * 4;

    const float* Ab = A + (size_t)(bm * 128) * K;
    const float* Bb = Bm + bn * 128;

    for (int k0 = 0; k0 < K; k0 += 8) {
        float4 av = *(const float4*)(Ab + (size_t)aRow * K + k0 + aCol);
        As[aCol + 0][aRow] = av.x;
        As[aCol + 1][aRow] = av.y;
        As[aCol + 2][aRow] = av.z;
        As[aCol + 3][aRow] = av.w;
        float4 bv = *(const float4*)(Bb + (size_t)(k0 + bRow) * N + bCol);
        *(float4*)&Bs[bRow][bCol] = bv;
        __syncthreads();

#pragma unroll
        for (int kk = 0; kk < 8; ++kk) {
            float a[8], b[8];
            *(float4*)(a)     = *(const float4*)&As[kk][ty * 8];
            *(float4*)(a + 4) = *(const float4*)&As[kk][ty * 8 + 4];
            *(float4*)(b)     = *(const float4*)&Bs[kk][tx * 8];
            *(float4*)(b + 4) = *(const float4*)&Bs[kk][tx * 8 + 4];
#pragma unroll
            for (int i = 0; i < 8; ++i)
#pragma unroll
                for (int j = 0; j < 8; ++j)
                    acc[i][j] = fmaf(a[i], b[j], acc[i][j]);
        }
        __syncthreads();
    }

#pragma unroll
    for (int i = 0; i < 8; ++i) {
        int row  = bm * 128 + ty * 8 + i;
        int colb = bn * 128 + tx * 8;
#pragma unroll
        for (int j = 0; j < 8; ++j) {
            int col = colb + j;
            float v = acc[i][j];
            if (EPI == 1)      v = fmaxf(v + bias[col], 0.0f);
            else if (EPI == 2) v = v + bias[col] + res[(size_t)row * N + col];
            C[(size_t)row * N + col] = v;
        }
    }
}

// ---------------- launch -----------------------------------------------------
extern "C" void kernel_launch(void* const* d_in, const int* in_sizes, int n_in,
                              void* d_out, int out_size)
{
    const float* points   = (const float*)d_in[0];
    const float* features = (const float*)d_in[1];
    const float* W_down   = (const float*)d_in[2];
    const float* b_down   = (const float*)d_in[3];
    const float* W_edge   = (const float*)d_in[4];
    const float* b_edge   = (const float*)d_in[5];
    const float* gamma    = (const float*)d_in[6];
    const float* beta     = (const float*)d_in[7];
    const float* mean     = (const float*)d_in[8];
    const float* var      = (const float*)d_in[9];
    const float* W_up     = (const float*)d_in[10];
    const float* b_up     = (const float*)d_in[11];
    float* out = (float*)d_out;

    void *p_fl, *p_wc, *p_ab, *p_local;
    cudaGetSymbolAddress(&p_fl,    g_feats_low);
    cudaGetSymbolAddress(&p_wc,    g_Wcomb);
    cudaGetSymbolAddress(&p_ab,    g_AB);
    cudaGetSymbolAddress(&p_local, g_local);

    // 1) prep: Wcomb + BN fold
    prep_kernel<<<256, 256>>>(W_edge, b_edge, gamma, beta, mean, var);

    // 2) KNN (independent of GEMM1; scheduler may overlap)
    knn_kernel<<<dim3(NN / 64, BB), 64>>>(points);

    // 3) feats_low = relu(features @ W_down + b_down)   [16384 x 256, K=1024]
    sgemm128<1><<<dim3(PP / 128, MM / 128), 256>>>(
        features, W_down, (float*)p_fl, MM, PP, DD, b_down, nullptr);

    // 4) AB = feats_low @ Wcomb                          [16384 x 512, K=256]
    sgemm128<0><<<dim3(2 * PP / 128, MM / 128), 256>>>(
        (const float*)p_fl, (const float*)p_wc, (float*)p_ab,
        MM, 2 * PP, PP, nullptr, nullptr);

    // 5) gather + BN + relu + max over K
    edge_max_kernel<<<MM, 256>>>();

    // 6) out = features + local @ W_up + b_up            [16384 x 1024, K=256]
    sgemm128<2><<<dim3(DD / 128, MM / 128), 256>>>(
        (const float*)p_local, W_up, out, MM, DD, PP, b_up, features);
}

// round 3
// speedup vs baseline: 1.9348x; 1.9348x over previous
#include <cuda_runtime.h>
#include <cuda_bf16.h>
#include <cstdint>
#include <cfloat>

#define BB   16
#define NN   1024
#define DD   1024
#define PP   256
#define KNB  16
#define MM   (BB * NN)     // 16384

// ===================== helpers ==============================================
__device__ __forceinline__ uint32_t smem_u32(const void* p) {
    uint32_t a;
    asm("{ .reg .u64 t; cvta.to.shared.u64 t, %1; cvt.u32.u64 %0, t; }" : "=r"(a) : "l"(p));
    return a;
}
__device__ __forceinline__ uint64_t cvta_g(const void* p) {
    uint64_t r; asm("cvta.to.global.u64 %0, %1;" : "=l"(r) : "l"(p)); return r;
}
#define SMEM_SWIZZLE_128B(off) ((off) ^ (((off) >> 3) & 0x70))

#define CP_ASYNC16(dst, src) \
    asm volatile("cp.async.cg.shared.global [%0], [%1], 16;" :: "r"(dst), "l"(src) : "memory")
#define CP_COMMIT() asm volatile("cp.async.commit_group;" ::: "memory")
#define CP_WAIT(n)  asm volatile("cp.async.wait_group %0;" :: "n"(n) : "memory")

#define LDSM_X4(r0, r1, r2, r3, addr) \
    asm volatile("ldmatrix.sync.aligned.m8n8.x4.shared.b16 {%0,%1,%2,%3}, [%4];" \
                 : "=r"(r0), "=r"(r1), "=r"(r2), "=r"(r3) : "r"(addr))

#define MMA_BF16(d, a, b) \
    asm volatile("mma.sync.aligned.m16n8k16.row.col.f32.bf16.bf16.f32 " \
                 "{%0,%1,%2,%3}, {%4,%5,%6,%7}, {%8,%9}, {%0,%1,%2,%3};" \
                 : "+f"((d)[0]), "+f"((d)[1]), "+f"((d)[2]), "+f"((d)[3]) \
                 : "r"((a)[0]), "r"((a)[1]), "r"((a)[2]), "r"((a)[3]), \
                   "r"((b)[0]), "r"((b)[1]))

// ===================== scratch ==============================================
__device__ __nv_bfloat16 g_fa_h[(size_t)MM * DD];
__device__ __nv_bfloat16 g_fa_l[(size_t)MM * DD];
__device__ __nv_bfloat16 g_wdT_h[PP * DD];
__device__ __nv_bfloat16 g_wdT_l[PP * DD];
__device__ __nv_bfloat16 g_wcT_h[2 * PP * PP];
__device__ __nv_bfloat16 g_wcT_l[2 * PP * PP];
__device__ __nv_bfloat16 g_wuT_h[DD * PP];
__device__ __nv_bfloat16 g_wuT_l[DD * PP];
__device__ __nv_bfloat16 g_fl_h[(size_t)MM * PP];
__device__ __nv_bfloat16 g_fl_l[(size_t)MM * PP];
__device__ float         g_AB[(size_t)MM * 2 * PP];
__device__ __nv_bfloat16 g_loc_h[(size_t)MM * PP];
__device__ __nv_bfloat16 g_loc_l[(size_t)MM * PP];
__device__ int           g_idx[MM * KNB];
__device__ float         g_s[PP];
__device__ float         g_t[PP];

__device__ __forceinline__ void split_f32(float v, __nv_bfloat16& h, __nv_bfloat16& l) {
    h = __float2bfloat16(v);
    l = __float2bfloat16(v - __bfloat162float(h));
}

// ===================== prep kernels =========================================
__global__ void split_features_kernel(const float4* __restrict__ f) {
    int i = blockIdx.x * blockDim.x + threadIdx.x;
    if (i >= MM * DD / 4) return;
    float4 v = f[i];
    __nv_bfloat16 hh[4], ll[4];
    split_f32(v.x, hh[0], ll[0]);
    split_f32(v.y, hh[1], ll[1]);
    split_f32(v.z, hh[2], ll[2]);
    split_f32(v.w, hh[3], ll[3]);
    *(uint2*)(g_fa_h + 4 * (size_t)i) = *(uint2*)hh;
    *(uint2*)(g_fa_l + 4 * (size_t)i) = *(uint2*)ll;
}

__global__ void prep_weights_kernel(const float* __restrict__ W_down,
                                    const float* __restrict__ W_edge,
                                    const float* __restrict__ W_up,
                                    const float* __restrict__ b_edge,
                                    const float* __restrict__ gamma,
                                    const float* __restrict__ beta,
                                    const float* __restrict__ mean,
                                    const float* __restrict__ var) {
    int t = blockIdx.x * blockDim.x + threadIdx.x;
    if (t < PP * DD) {
        float v = W_down[(size_t)(t & 1023) * PP + (t >> 10)];
        split_f32(v, g_wdT_h[t], g_wdT_l[t]);
    }
    if (t < DD * PP) {
        float v = W_up[(size_t)(t & 255) * DD + (t >> 8)];
        split_f32(v, g_wuT_h[t], g_wuT_l[t]);
    }
    if (t < 2 * PP * PP) {
        int p = t >> 8, f = t & 255;
        float v = (p < PP) ? (W_edge[f * PP + p] - W_edge[(f + PP) * PP + p])
                           : W_edge[(f + PP) * PP + (p - PP)];
        split_f32(v, g_wcT_h[t], g_wcT_l[t]);
    }
    if (t < PP) {
        float rs = rsqrtf(var[t] + 1e-5f);
        float sv = gamma[t] * rs;
        g_s[t] = sv;
        g_t[t] = beta[t] - mean[t] * sv + sv * b_edge[t];
    }
}

// ===================== KNN ==================================================
__global__ __launch_bounds__(64) void knn_kernel(const float* __restrict__ pts) {
    const int b = blockIdx.y;
    const int n = blockIdx.x * 64 + threadIdx.x;

    __shared__ float sx[NN], sy[NN], sz[NN], ssq[NN];
    for (int m = threadIdx.x; m < NN; m += 64) {
        float x = pts[((size_t)b * NN + m) * 3 + 0];
        float y = pts[((size_t)b * NN + m) * 3 + 1];
        float z = pts[((size_t)b * NN + m) * 3 + 2];
        sx[m] = x; sy[m] = y; sz[m] = z;
        ssq[m] = x * x + y * y + z * z;
    }
    __syncthreads();

    const float px = sx[n], py = sy[n], pz = sz[n], psq = ssq[n];
    float bd[KNB]; int bi[KNB];
#pragma unroll
    for (int j = 0; j < KNB; ++j) { bd[j] = FLT_MAX; bi[j] = 0; }

    for (int m = 0; m < NN; ++m) {
        float dot = px * sx[m] + py * sy[m] + pz * sz[m];
        float d = psq + ssq[m] - 2.0f * dot;
        if (d < bd[KNB - 1]) {
            float dc = d; int ic = m;
#pragma unroll
            for (int j = 0; j < KNB; ++j) {
                if (dc < bd[j]) {
                    float td = bd[j]; bd[j] = dc; dc = td;
                    int   ti = bi[j]; bi[j] = ic; ic = ti;
                }
            }
        }
    }
    int base = ((size_t)b * NN + n) * KNB;
#pragma unroll
    for (int j = 0; j < KNB; ++j) g_idx[base + j] = bi[j];
}

// ===================== edge gather + BN + relu + max ========================
__global__ __launch_bounds__(256) void edge_max_kernel() {
    const int bn = blockIdx.x;
    const int p  = threadIdx.x;
    const int b  = bn >> 10;

    __shared__ int sidx[KNB];
    if (p < KNB) sidx[p] = g_idx[bn * KNB + p];
    __syncthreads();

    const float a  = g_AB[(size_t)bn * 512 + p];
    const float sp = g_s[p];
    const float tp = g_t[p];

    float acc = 0.0f;
#pragma unroll
    for (int k = 0; k < KNB; ++k) {
        float v = g_AB[(size_t)((b << 10) + sidx[k]) * 512 + PP + p];
        float h = fmaf(sp, a + v, tp);
        acc = fmaxf(acc, h);
    }
    size_t o = (size_t)bn * PP + p;
    split_f32(acc, g_loc_h[o], g_loc_l[o]);
}

// ===================== mma.sync split-bf16 GEMM =============================
// C[M,N] = (Ah+Al)[M,K] @ (Bh+Bl)^T, B stored [N][K] (K-major).
// Tile: CTA 128x128, K-chunk 32. SMEM row = 128B: [32 hi bf16 | 32 lo bf16].
// EPI 0: Cf = acc ; EPI 1: relu(acc+bias) -> split bf16 ; EPI 2: acc+bias+res.
template <int EPI>
__global__ void __launch_bounds__(256, 2) gemm_mma(
    const __nv_bfloat16* __restrict__ Ah, const __nv_bfloat16* __restrict__ Al,
    const __nv_bfloat16* __restrict__ Bh, const __nv_bfloat16* __restrict__ Bl,
    int K, int Nc,
    float* __restrict__ Cf,
    __nv_bfloat16* __restrict__ Ch, __nv_bfloat16* __restrict__ Cl,
    const float* __restrict__ bias, const float* __restrict__ res)
{
    extern __shared__ char smraw[];
    const uint32_t smb = smem_u32(smraw);
    // buffers: buf b: A at b*32768, B at b*32768 + 16384
    const int tid = threadIdx.x, lane = tid & 31, wid = tid >> 5;
    const int warp_m = wid & 3, warp_n = wid >> 2;
    const int bm = blockIdx.y, bn = blockIdx.x;

    const uint64_t gAh = cvta_g(Ah + (size_t)(bm * 128) * K);
    const uint64_t gAl = cvta_g(Al + (size_t)(bm * 128) * K);
    const uint64_t gBh = cvta_g(Bh + (size_t)(bn * 128) * K);
    const uint64_t gBl = cvta_g(Bl + (size_t)(bn * 128) * K);

    // cp.async mapping: idx in [0,1024): row=idx>>3, granule g=idx&7
    // g<4 -> hi bf16 k = 8g..8g+7 ; g>=4 -> lo, k = 8(g-4)..
    const int nk = K >> 5;

    // ldmatrix per-lane addressing
    const int grp = lane >> 3, rr = lane & 7;
    // A: row = warp_m*32 + mt*16 + (grp&1)*8 + rr ; byte = h*64 + s*32 + (grp>>1)*16
    int a_row0 = warp_m * 32 + ((grp & 1) << 3) + rr;
    const int kadd_a = (grp >> 1) << 4;
    // B: n = warp_n*64 + jg*32 + p*16 + (grp>>1)*8 + rr ; byte = h*64 + s*32 + (grp&1)*16
    int b_row0 = warp_n * 64 + ((grp >> 1) << 3) + rr;
    const int kadd_b = (grp & 1) << 4;

    float acc[2][8][4];
#pragma unroll
    for (int i = 0; i < 2; ++i)
#pragma unroll
        for (int j = 0; j < 8; ++j)
#pragma unroll
            for (int c = 0; c < 4; ++c) acc[i][j][c] = 0.0f;

    // ---- prologue: load chunk 0 into buffer 0
#pragma unroll
    for (int i = 0; i < 4; ++i) {
        int idx = i * 256 + tid;
        int row = idx >> 3, g = idx & 7;
        int kel = (g & 3) * 8;
        uint32_t dst = SMEM_SWIZZLE_128B((uint32_t)(row * 128 + g * 16));
        CP_ASYNC16(smb + dst, (g < 4 ? gAh : gAl) + ((size_t)row * K + kel) * 2);
        CP_ASYNC16(smb + 16384 + dst, (g < 4 ? gBh : gBl) + ((size_t)row * K + kel) * 2);
    }
    CP_COMMIT();

    for (int kc = 0; kc < nk; ++kc) {
        if (kc + 1 < nk) {
            const int kof = (kc + 1) * 32;
            const uint32_t bb = ((kc + 1) & 1) * 32768;
#pragma unroll
            for (int i = 0; i < 4; ++i) {
                int idx = i * 256 + tid;
                int row = idx >> 3, g = idx & 7;
                int kel = kof + (g & 3) * 8;
                uint32_t dst = SMEM_SWIZZLE_128B((uint32_t)(row * 128 + g * 16));
                CP_ASYNC16(smb + bb + dst, (g < 4 ? gAh : gAl) + ((size_t)row * K + kel) * 2);
                CP_ASYNC16(smb + bb + 16384 + dst, (g < 4 ? gBh : gBl) + ((size_t)row * K + kel) * 2);
            }
            CP_COMMIT();
            CP_WAIT(1);
        } else {
            CP_WAIT(0);
        }
        __syncthreads();

        const uint32_t bufA = smb + (kc & 1) * 32768;
        const uint32_t bufB = bufA + 16384;

#pragma unroll
        for (int s = 0; s < 2; ++s) {
            uint32_t ahf[2][4], alf[2][4];
#pragma unroll
            for (int mt = 0; mt < 2; ++mt) {
                int row = a_row0 + mt * 16;
                uint32_t rb = bufA + row * 128;
                uint32_t xr = (row & 7) << 4;
                uint32_t byH = (uint32_t)(s * 32 + kadd_a);
                uint32_t byL = byH + 64;
                LDSM_X4(ahf[mt][0], ahf[mt][1], ahf[mt][2], ahf[mt][3], rb + (byH ^ xr));
                LDSM_X4(alf[mt][0], alf[mt][1], alf[mt][2], alf[mt][3], rb + (byL ^ xr));
            }
#pragma unroll
            for (int jg = 0; jg < 2; ++jg) {
                uint32_t bhf[4][2], blf[4][2];
#pragma unroll
                for (int p = 0; p < 2; ++p) {
                    int row = b_row0 + jg * 32 + p * 16;
                    uint32_t rb = bufB + row * 128;
                    uint32_t xr = (row & 7) << 4;
                    uint32_t byH = (uint32_t)(s * 32 + kadd_b);
                    uint32_t byL = byH + 64;
                    LDSM_X4(bhf[2 * p][0], bhf[2 * p][1], bhf[2 * p + 1][0], bhf[2 * p + 1][1],
                            rb + (byH ^ xr));
                    LDSM_X4(blf[2 * p][0], blf[2 * p][1], blf[2 * p + 1][0], blf[2 * p + 1][1],
                            rb + (byL ^ xr));
                }
#pragma unroll
                for (int mt = 0; mt < 2; ++mt)
#pragma unroll
                    for (int j = 0; j < 4; ++j) {
                        float* d = acc[mt][jg * 4 + j];
                        MMA_BF16(d, ahf[mt], bhf[j]);
                        MMA_BF16(d, ahf[mt], blf[j]);
                        MMA_BF16(d, alf[mt], bhf[j]);
                    }
            }
        }
        __syncthreads();
    }

    // ---- epilogue
#pragma unroll
    for (int mt = 0; mt < 2; ++mt) {
#pragma unroll
        for (int half = 0; half < 2; ++half) {
            size_t row = (size_t)bm * 128 + warp_m * 32 + mt * 16 + half * 8 + (lane >> 2);
#pragma unroll
            for (int j = 0; j < 8; ++j) {
                int col = bn * 128 + warp_n * 64 + j * 8 + 2 * (lane & 3);
                float v0 = acc[mt][j][half * 2 + 0];
                float v1 = acc[mt][j][half * 2 + 1];
                if (EPI == 0) {
                    *(float2*)(Cf + row * Nc + col) = make_float2(v0, v1);
                } else if (EPI == 1) {
                    v0 = fmaxf(v0 + bias[col], 0.0f);
                    v1 = fmaxf(v1 + bias[col + 1], 0.0f);
                    __nv_bfloat16 h0, l0, h1, l1;
                    split_f32(v0, h0, l0);
                    split_f32(v1, h1, l1);
                    __nv_bfloat162 hh; hh.x = h0; hh.y = h1;
                    __nv_bfloat162 ll; ll.x = l0; ll.y = l1;
                    *(__nv_bfloat162*)(Ch + row * Nc + col) = hh;
                    *(__nv_bfloat162*)(Cl + row * Nc + col) = ll;
                } else {
                    float2 r = *(const float2*)(res + row * Nc + col);
                    *(float2*)(Cf + row * Nc + col) =
                        make_float2(v0 + bias[col] + r.x, v1 + bias[col + 1] + r.y);
                }
            }
        }
    }
}

// ===================== launch ===============================================
extern "C" void kernel_launch(void* const* d_in, const int* in_sizes, int n_in,
                              void* d_out, int out_size)
{
    const float* points   = (const float*)d_in[0];
    const float* features = (const float*)d_in[1];
    const float* W_down   = (const float*)d_in[2];
    const float* b_down   = (const float*)d_in[3];
    const float* W_edge   = (const float*)d_in[4];
    const float* b_edge   = (const float*)d_in[5];
    const float* gamma    = (const float*)d_in[6];
    const float* beta     = (const float*)d_in[7];
    const float* mean     = (const float*)d_in[8];
    const float* var      = (const float*)d_in[9];
    const float* W_up     = (const float*)d_in[10];
    const float* b_up     = (const float*)d_in[11];
    float* out = (float*)d_out;

    const int SMEM_DYN = 65536;
    static bool attr_done = false;
    if (!attr_done) {
        cudaFuncSetAttribute(gemm_mma<0>, cudaFuncAttributeMaxDynamicSharedMemorySize, SMEM_DYN);
        cudaFuncSetAttribute(gemm_mma<1>, cudaFuncAttributeMaxDynamicSharedMemorySize, SMEM_DYN);
        cudaFuncSetAttribute(gemm_mma<2>, cudaFuncAttributeMaxDynamicSharedMemorySize, SMEM_DYN);
        attr_done = true;
    }

    void *p_fah, *p_fal, *p_wdh, *p_wdl, *p_wch, *p_wcl, *p_wuh, *p_wul;
    void *p_flh, *p_fll, *p_ab, *p_loh, *p_lol;
    cudaGetSymbolAddress(&p_fah, g_fa_h);  cudaGetSymbolAddress(&p_fal, g_fa_l);
    cudaGetSymbolAddress(&p_wdh, g_wdT_h); cudaGetSymbolAddress(&p_wdl, g_wdT_l);
    cudaGetSymbolAddress(&p_wch, g_wcT_h); cudaGetSymbolAddress(&p_wcl, g_wcT_l);
    cudaGetSymbolAddress(&p_wuh, g_wuT_h); cudaGetSymbolAddress(&p_wul, g_wuT_l);
    cudaGetSymbolAddress(&p_flh, g_fl_h);  cudaGetSymbolAddress(&p_fll, g_fl_l);
    cudaGetSymbolAddress(&p_ab,  g_AB);
    cudaGetSymbolAddress(&p_loh, g_loc_h); cudaGetSymbolAddress(&p_lol, g_loc_l);

    // 1) prep + split + KNN
    prep_weights_kernel<<<(PP * DD + 255) / 256, 256>>>(
        W_down, W_edge, W_up, b_edge, gamma, beta, mean, var);
    split_features_kernel<<<(MM * DD / 4 + 255) / 256, 256>>>((const float4*)features);
    knn_kernel<<<dim3(NN / 64, BB), 64>>>(points);

    // 2) feats_low = relu(features @ W_down + b_down)  [M=16384, N=256, K=1024]
    gemm_mma<1><<<dim3(PP / 128, MM / 128), 256, SMEM_DYN>>>(
        (const __nv_bfloat16*)p_fah, (const __nv_bfloat16*)p_fal,
        (const __nv_bfloat16*)p_wdh, (const __nv_bfloat16*)p_wdl,
        DD, PP, nullptr,
        (__nv_bfloat16*)p_flh, (__nv_bfloat16*)p_fll, b_down, nullptr);

    // 3) AB = feats_low @ Wcomb                        [M, N=512, K=256]
    gemm_mma<0><<<dim3(2 * PP / 128, MM / 128), 256, SMEM_DYN>>>(
        (const __nv_bfloat16*)p_flh, (const __nv_bfloat16*)p_fll,
        (const __nv_bfloat16*)p_wch, (const __nv_bfloat16*)p_wcl,
        PP, 2 * PP, (float*)p_ab, nullptr, nullptr, nullptr, nullptr);

    // 4) gather + BN + relu + max over K -> local (split bf16)
    edge_max_kernel<<<MM, 256>>>();

    // 5) out = features + local @ W_up + b_up          [M, N=1024, K=256]
    gemm_mma<2><<<dim3(DD / 128, MM / 128), 256, SMEM_DYN>>>(
        (const __nv_bfloat16*)p_loh, (const __nv_bfloat16*)p_lol,
        (const __nv_bfloat16*)p_wuh, (const __nv_bfloat16*)p_wul,
        PP, DD, out, nullptr, nullptr, b_up, features);
}

// round 4
// speedup vs baseline: 2.0993x; 1.0850x over previous
#include <cuda_runtime.h>
#include <cuda_bf16.h>
#include <cuda_fp16.h>
#include <cstdint>
#include <cfloat>

#define BB   16
#define NN   1024
#define DD   1024
#define PP   256
#define KNB  16
#define MM   (BB * NN)     // 16384

// ===================== helpers ==============================================
__device__ __forceinline__ uint32_t smem_u32(const void* p) {
    uint32_t a;
    asm("{ .reg .u64 t; cvta.to.shared.u64 t, %1; cvt.u32.u64 %0, t; }" : "=r"(a) : "l"(p));
    return a;
}
__device__ __forceinline__ uint64_t cvta_g(const void* p) {
    uint64_t r; asm("cvta.to.global.u64 %0, %1;" : "=l"(r) : "l"(p)); return r;
}
#define SMEM_SWIZZLE_128B(off) ((off) ^ (((off) >> 3) & 0x70))

#define CP_ASYNC16(dst, src) \
    asm volatile("cp.async.cg.shared.global [%0], [%1], 16;" :: "r"(dst), "l"(src) : "memory")
#define CP_COMMIT() asm volatile("cp.async.commit_group;" ::: "memory")
#define CP_WAIT(n)  asm volatile("cp.async.wait_group %0;" :: "n"(n) : "memory")

#define LDSM_X4(r0, r1, r2, r3, addr) \
    asm volatile("ldmatrix.sync.aligned.m8n8.x4.shared.b16 {%0,%1,%2,%3}, [%4];" \
                 : "=r"(r0), "=r"(r1), "=r"(r2), "=r"(r3) : "r"(addr))

#define MMA_BF16(d, a, b) \
    asm volatile("mma.sync.aligned.m16n8k16.row.col.f32.bf16.bf16.f32 " \
                 "{%0,%1,%2,%3}, {%4,%5,%6,%7}, {%8,%9}, {%0,%1,%2,%3};" \
                 : "+f"((d)[0]), "+f"((d)[1]), "+f"((d)[2]), "+f"((d)[3]) \
                 : "r"((a)[0]), "r"((a)[1]), "r"((a)[2]), "r"((a)[3]), \
                   "r"((b)[0]), "r"((b)[1]))

#define MMA_F16(d, a, b) \
    asm volatile("mma.sync.aligned.m16n8k16.row.col.f32.f16.f16.f32 " \
                 "{%0,%1,%2,%3}, {%4,%5,%6,%7}, {%8,%9}, {%0,%1,%2,%3};" \
                 : "+f"((d)[0]), "+f"((d)[1]), "+f"((d)[2]), "+f"((d)[3]) \
                 : "r"((a)[0]), "r"((a)[1]), "r"((a)[2]), "r"((a)[3]), \
                   "r"((b)[0]), "r"((b)[1]))

// ===================== scratch ==============================================
__device__ __nv_bfloat16 g_fa_h[(size_t)MM * DD];   // features hi (bf16)
__device__ __nv_bfloat16 g_fa_l[(size_t)MM * DD];   // features lo (bf16)
__device__ __nv_bfloat16 g_wdT_h[PP * DD];          // W_down^T hi [256][1024]
__device__ __nv_bfloat16 g_wdT_l[PP * DD];
__device__ __half        g_wcT_h[2 * PP * PP];      // Wcomb^T hi/lo fp16 [512][256]
__device__ __half        g_wcT_l[2 * PP * PP];
__device__ __half        g_wuT_h[DD * PP];          // W_up^T hi/lo fp16 [1024][256]
__device__ __half        g_wuT_l[DD * PP];
__device__ __half        g_fl[(size_t)MM * PP];     // feats_low fp16 [M][256]
__device__ __half        g_AB[(size_t)MM * 2 * PP]; // fp16 [M][0:256]=A',[256:512]=Bv
__device__ __half        g_loc[(size_t)MM * PP];    // local fp16 [M][256]
__device__ int           g_idx[MM * KNB];
__device__ float         g_s[PP];
__device__ float         g_t[PP];

__device__ __forceinline__ void split_bf(float v, __nv_bfloat16& h, __nv_bfloat16& l) {
    h = __float2bfloat16(v);
    l = __float2bfloat16(v - __bfloat162float(h));
}
__device__ __forceinline__ void split_hf(float v, __half& h, __half& l) {
    h = __float2half_rn(v);
    l = __float2half_rn(v - __half2float(h));
}

// ===================== prep kernels =========================================
__global__ void split_features_kernel(const float4* __restrict__ f) {
    int i = blockIdx.x * blockDim.x + threadIdx.x;
    if (i >= MM * DD / 4) return;
    float4 v = f[i];
    __nv_bfloat16 hh[4], ll[4];
    split_bf(v.x, hh[0], ll[0]);
    split_bf(v.y, hh[1], ll[1]);
    split_bf(v.z, hh[2], ll[2]);
    split_bf(v.w, hh[3], ll[3]);
    *(uint2*)(g_fa_h + 4 * (size_t)i) = *(uint2*)hh;
    *(uint2*)(g_fa_l + 4 * (size_t)i) = *(uint2*)ll;
}

__global__ void prep_weights_kernel(const float* __restrict__ W_down,
                                    const float* __restrict__ W_edge,
                                    const float* __restrict__ W_up,
                                    const float* __restrict__ b_edge,
                                    const float* __restrict__ gamma,
                                    const float* __restrict__ beta,
                                    const float* __restrict__ mean,
                                    const float* __restrict__ var) {
    int t = blockIdx.x * blockDim.x + threadIdx.x;
    if (t < PP * DD) {  // W_down^T bf16 hi/lo
        float v = W_down[(size_t)(t & 1023) * PP + (t >> 10)];
        split_bf(v, g_wdT_h[t], g_wdT_l[t]);
    }
    if (t < DD * PP) {  // W_up^T fp16 hi/lo
        float v = W_up[(size_t)(t & 255) * DD + (t >> 8)];
        split_hf(v, g_wuT_h[t], g_wuT_l[t]);
    }
    if (t < 2 * PP * PP) {  // Wcomb^T fp16 hi/lo
        int p = t >> 8, f = t & 255;
        float v = (p < PP) ? (W_edge[f * PP + p] - W_edge[(f + PP) * PP + p])
                           : W_edge[(f + PP) * PP + (p - PP)];
        split_hf(v, g_wcT_h[t], g_wcT_l[t]);
    }
    if (t < PP) {
        float rs = rsqrtf(var[t] + 1e-5f);
        float sv = gamma[t] * rs;
        g_s[t] = sv;
        g_t[t] = beta[t] - mean[t] * sv + sv * b_edge[t];
    }
}

// ===================== KNN ==================================================
__global__ __launch_bounds__(64) void knn_kernel(const float* __restrict__ pts) {
    const int b = blockIdx.y;
    const int n = blockIdx.x * 64 + threadIdx.x;

    __shared__ float sx[NN], sy[NN], sz[NN], ssq[NN];
    for (int m = threadIdx.x; m < NN; m += 64) {
        float x = pts[((size_t)b * NN + m) * 3 + 0];
        float y = pts[((size_t)b * NN + m) * 3 + 1];
        float z = pts[((size_t)b * NN + m) * 3 + 2];
        sx[m] = x; sy[m] = y; sz[m] = z;
        ssq[m] = x * x + y * y + z * z;
    }
    __syncthreads();

    const float px = sx[n], py = sy[n], pz = sz[n], psq = ssq[n];
    float bd[KNB]; int bi[KNB];
#pragma unroll
    for (int j = 0; j < KNB; ++j) { bd[j] = FLT_MAX; bi[j] = 0; }

    for (int m = 0; m < NN; ++m) {
        float dot = px * sx[m] + py * sy[m] + pz * sz[m];
        float d = psq + ssq[m] - 2.0f * dot;
        if (d < bd[KNB - 1]) {
            float dc = d; int ic = m;
#pragma unroll
            for (int j = 0; j < KNB; ++j) {
                if (dc < bd[j]) {
                    float td = bd[j]; bd[j] = dc; dc = td;
                    int   ti = bi[j]; bi[j] = ic; ic = ti;
                }
            }
        }
    }
    int base = ((size_t)b * NN + n) * KNB;
#pragma unroll
    for (int j = 0; j < KNB; ++j) g_idx[base + j] = bi[j];
}

// ===================== edge gather + BN + relu + max ========================
__global__ __launch_bounds__(256) void edge_max_kernel() {
    const int bn = blockIdx.x;
    const int p  = threadIdx.x;
    const int b  = bn >> 10;

    __shared__ int sidx[KNB];
    if (p < KNB) sidx[p] = g_idx[bn * KNB + p];
    __syncthreads();

    const float a  = __half2float(g_AB[(size_t)bn * 512 + p]);
    const float sp = g_s[p];
    const float tp = g_t[p];

    float acc = 0.0f;
#pragma unroll
    for (int k = 0; k < KNB; ++k) {
        float v = __half2float(g_AB[(size_t)((b << 10) + sidx[k]) * 512 + PP + p]);
        float h = fmaf(sp, a + v, tp);
        acc = fmaxf(acc, h);
    }
    g_loc[(size_t)bn * PP + p] = __float2half_rn(acc);
}

// ===================== GEMM1: bf16 3-term, 3-stage, k-chunk 32 ==============
// feats_low = relu(features @ W_down^T' + b_down), stored fp16.
__global__ void __launch_bounds__(256, 2) gemm_bf16_3t(
    const __nv_bfloat16* __restrict__ Ah, const __nv_bfloat16* __restrict__ Al,
    const __nv_bfloat16* __restrict__ Bh, const __nv_bfloat16* __restrict__ Bl,
    int K, int Nc, __half* __restrict__ C, const float* __restrict__ bias)
{
    extern __shared__ char smraw[];
    const uint32_t smb = smem_u32(smraw);   // 3 buffers x 32KB: [A 16KB | B 16KB]
    const int tid = threadIdx.x, lane = tid & 31, wid = tid >> 5;
    const int warp_m = wid & 3, warp_n = wid >> 2;
    const int bm = blockIdx.y, bn = blockIdx.x;

    const uint64_t gAh = cvta_g(Ah + (size_t)(bm * 128) * K);
    const uint64_t gAl = cvta_g(Al + (size_t)(bm * 128) * K);
    const uint64_t gBh = cvta_g(Bh + (size_t)(bn * 128) * K);
    const uint64_t gBl = cvta_g(Bl + (size_t)(bn * 128) * K);
    const int nk = K >> 5;

    const int grp = lane >> 3, rr = lane & 7;
    const int a_row0 = warp_m * 32 + ((grp & 1) << 3) + rr;
    const int kadd_a = (grp >> 1) << 4;
    const int b_row0 = warp_n * 64 + ((grp >> 1) << 3) + rr;
    const int kadd_b = (grp & 1) << 4;

    float acc[2][8][4];
#pragma unroll
    for (int i = 0; i < 2; ++i)
#pragma unroll
        for (int j = 0; j < 8; ++j)
#pragma unroll
            for (int c = 0; c < 4; ++c) acc[i][j][c] = 0.0f;

    auto issue = [&](int kc) {
        const uint32_t bb = (uint32_t)(kc % 3) * 32768u;
        const int kof = kc * 32;
#pragma unroll
        for (int i = 0; i < 4; ++i) {
            int idx = i * 256 + tid;
            int row = idx >> 3, g = idx & 7;
            int kel = kof + (g & 3) * 8;
            uint32_t dst = SMEM_SWIZZLE_128B((uint32_t)(row * 128 + g * 16));
            CP_ASYNC16(smb + bb + dst, (g < 4 ? gAh : gAl) + ((size_t)row * K + kel) * 2);
            CP_ASYNC16(smb + bb + 16384 + dst, (g < 4 ? gBh : gBl) + ((size_t)row * K + kel) * 2);
        }
    };

    issue(0); CP_COMMIT();
    if (nk > 1) issue(1);
    CP_COMMIT();

    for (int kc = 0; kc < nk; ++kc) {
        CP_WAIT(1);
        __syncthreads();
        if (kc + 2 < nk) issue(kc + 2);
        CP_COMMIT();

        const uint32_t bufA = smb + (uint32_t)(kc % 3) * 32768u;
        const uint32_t bufB = bufA + 16384;

#pragma unroll
        for (int s = 0; s < 2; ++s) {
            uint32_t ahf[2][4], alf[2][4];
#pragma unroll
            for (int mt = 0; mt < 2; ++mt) {
                int row = a_row0 + mt * 16;
                uint32_t rb = bufA + row * 128;
                uint32_t xr = (row & 7) << 4;
                uint32_t byH = (uint32_t)(s * 32 + kadd_a);
                LDSM_X4(ahf[mt][0], ahf[mt][1], ahf[mt][2], ahf[mt][3], rb + (byH ^ xr));
                LDSM_X4(alf[mt][0], alf[mt][1], alf[mt][2], alf[mt][3], rb + ((byH + 64) ^ xr));
            }
#pragma unroll
            for (int jg = 0; jg < 2; ++jg) {
                uint32_t bhf[4][2], blf[4][2];
#pragma unroll
                for (int p = 0; p < 2; ++p) {
                    int row = b_row0 + jg * 32 + p * 16;
                    uint32_t rb = bufB + row * 128;
                    uint32_t xr = (row & 7) << 4;
                    uint32_t byH = (uint32_t)(s * 32 + kadd_b);
                    LDSM_X4(bhf[2 * p][0], bhf[2 * p][1], bhf[2 * p + 1][0], bhf[2 * p + 1][1],
                            rb + (byH ^ xr));
                    LDSM_X4(blf[2 * p][0], blf[2 * p][1], blf[2 * p + 1][0], blf[2 * p + 1][1],
                            rb + ((byH + 64) ^ xr));
                }
#pragma unroll
                for (int mt = 0; mt < 2; ++mt)
#pragma unroll
                    for (int j = 0; j < 4; ++j) {
                        float* d = acc[mt][jg * 4 + j];
                        MMA_BF16(d, ahf[mt], bhf[j]);
                        MMA_BF16(d, ahf[mt], blf[j]);
                        MMA_BF16(d, alf[mt], bhf[j]);
                    }
            }
        }
        __syncthreads();
    }

#pragma unroll
    for (int mt = 0; mt < 2; ++mt)
#pragma unroll
        for (int half = 0; half < 2; ++half) {
            size_t row = (size_t)bm * 128 + warp_m * 32 + mt * 16 + half * 8 + (lane >> 2);
#pragma unroll
            for (int j = 0; j < 8; ++j) {
                int col = bn * 128 + warp_n * 64 + j * 8 + 2 * (lane & 3);
                float v0 = fmaxf(acc[mt][j][half * 2 + 0] + bias[col], 0.0f);
                float v1 = fmaxf(acc[mt][j][half * 2 + 1] + bias[col + 1], 0.0f);
                __half2 hv; hv.x = __float2half_rn(v0); hv.y = __float2half_rn(v1);
                *(__half2*)(C + row * Nc + col) = hv;
            }
        }
}

// ===================== GEMM fp16 2-term, 2-stage, k-chunk 64 ================
// C = A(fp16) @ (Bh+Bl)^T ; B stored [N][K].
// EPI 0: store fp16 ; EPI 2: fp32 store acc + bias[col] + res[row,col].
template <int EPI>
__global__ void __launch_bounds__(256, 2) gemm_f16_2t(
    const __half* __restrict__ A,
    const __half* __restrict__ Bh, const __half* __restrict__ Bl,
    int K, int Nc,
    __half* __restrict__ Ch, float* __restrict__ Cf,
    const float* __restrict__ bias, const float* __restrict__ res)
{
    extern __shared__ char smraw[];
    const uint32_t smb = smem_u32(smraw);   // 2 buffers x 48KB: [A 16KB | Bh 16KB | Bl 16KB]
    const int tid = threadIdx.x, lane = tid & 31, wid = tid >> 5;
    const int warp_m = wid & 3, warp_n = wid >> 2;
    const int bm = blockIdx.y, bn = blockIdx.x;

    const uint64_t gA  = cvta_g(A  + (size_t)(bm * 128) * K);
    const uint64_t gBh = cvta_g(Bh + (size_t)(bn * 128) * K);
    const uint64_t gBl = cvta_g(Bl + (size_t)(bn * 128) * K);
    const int nk = K >> 6;

    const int grp = lane >> 3, rr = lane & 7;
    const int a_row0 = warp_m * 32 + ((grp & 1) << 3) + rr;
    const int kadd_a = (grp >> 1) << 4;
    const int b_row0 = warp_n * 64 + ((grp >> 1) << 3) + rr;
    const int kadd_b = (grp & 1) << 4;

    float acc[2][8][4];
#pragma unroll
    for (int i = 0; i < 2; ++i)
#pragma unroll
        for (int j = 0; j < 8; ++j)
#pragma unroll
            for (int c = 0; c < 4; ++c) acc[i][j][c] = 0.0f;

    auto issue = [&](int kc) {
        const uint32_t bb = (uint32_t)(kc & 1) * 49152u;
        const int kof = kc * 64;
#pragma unroll
        for (int i = 0; i < 4; ++i) {
            int idx = i * 256 + tid;
            int row = idx >> 3, g = idx & 7;
            int kel = kof + g * 8;
            uint32_t dst = SMEM_SWIZZLE_128B((uint32_t)(row * 128 + g * 16));
            size_t src = (size_t)row * K + kel;
            CP_ASYNC16(smb + bb + dst,         gA  + src * 2);
            CP_ASYNC16(smb + bb + 16384 + dst, gBh + src * 2);
            CP_ASYNC16(smb + bb + 32768 + dst, gBl + src * 2);
        }
    };

    issue(0); CP_COMMIT();

    for (int kc = 0; kc < nk; ++kc) {
        if (kc + 1 < nk) issue(kc + 1);
        CP_COMMIT();
        CP_WAIT(1);
        __syncthreads();

        const uint32_t bufA  = smb + (uint32_t)(kc & 1) * 49152u;
        const uint32_t bufBh = bufA + 16384;
        const uint32_t bufBl = bufA + 32768;

#pragma unroll
        for (int s = 0; s < 4; ++s) {
            uint32_t af[2][4];
#pragma unroll
            for (int mt = 0; mt < 2; ++mt) {
                int row = a_row0 + mt * 16;
                uint32_t rb = bufA + row * 128;
                uint32_t xr = (row & 7) << 4;
                LDSM_X4(af[mt][0], af[mt][1], af[mt][2], af[mt][3],
                        rb + (((uint32_t)(s * 32 + kadd_a)) ^ xr));
            }
#pragma unroll
            for (int jg = 0; jg < 2; ++jg) {
                uint32_t bh[4][2], bl[4][2];
#pragma unroll
                for (int p = 0; p < 2; ++p) {
                    int row = b_row0 + jg * 32 + p * 16;
                    uint32_t xr = (row & 7) << 4;
                    uint32_t by = (uint32_t)(s * 32 + kadd_b);
                    LDSM_X4(bh[2 * p][0], bh[2 * p][1], bh[2 * p + 1][0], bh[2 * p + 1][1],
                            bufBh + row * 128 + (by ^ xr));
                    LDSM_X4(bl[2 * p][0], bl[2 * p][1], bl[2 * p + 1][0], bl[2 * p + 1][1],
                            bufBl + row * 128 + (by ^ xr));
                }
#pragma unroll
                for (int mt = 0; mt < 2; ++mt)
#pragma unroll
                    for (int j = 0; j < 4; ++j) {
                        float* d = acc[mt][jg * 4 + j];
                        MMA_F16(d, af[mt], bh[j]);
                        MMA_F16(d, af[mt], bl[j]);
                    }
            }
        }
        __syncthreads();
    }

#pragma unroll
    for (int mt = 0; mt < 2; ++mt)
#pragma unroll
        for (int half = 0; half < 2; ++half) {
            size_t row = (size_t)bm * 128 + warp_m * 32 + mt * 16 + half * 8 + (lane >> 2);
#pragma unroll
            for (int j = 0; j < 8; ++j) {
                int col = bn * 128 + warp_n * 64 + j * 8 + 2 * (lane & 3);
                float v0 = acc[mt][j][half * 2 + 0];
                float v1 = acc[mt][j][half * 2 + 1];
                if (EPI == 0) {
                    __half2 hv; hv.x = __float2half_rn(v0); hv.y = __float2half_rn(v1);
                    *(__half2*)(Ch + row * Nc + col) = hv;
                } else {
                    float2 r = *(const float2*)(res + row * Nc + col);
                    *(float2*)(Cf + row * Nc + col) =
                        make_float2(v0 + bias[col] + r.x, v1 + bias[col + 1] + r.y);
                }
            }
        }
}

// ===================== launch ===============================================
extern "C" void kernel_launch(void* const* d_in, const int* in_sizes, int n_in,
                              void* d_out, int out_size)
{
    const float* points   = (const float*)d_in[0];
    const float* features = (const float*)d_in[1];
    const float* W_down   = (const float*)d_in[2];
    const float* b_down   = (const float*)d_in[3];
    const float* W_edge   = (const float*)d_in[4];
    const float* b_edge   = (const float*)d_in[5];
    const float* gamma    = (const float*)d_in[6];
    const float* beta     = (const float*)d_in[7];
    const float* mean     = (const float*)d_in[8];
    const float* var      = (const float*)d_in[9];
    const float* W_up     = (const float*)d_in[10];
    const float* b_up     = (const float*)d_in[11];
    float* out = (float*)d_out;

    const int SMEM_DYN = 98304;
    static bool attr_done = false;
    if (!attr_done) {
        cudaFuncSetAttribute(gemm_bf16_3t, cudaFuncAttributeMaxDynamicSharedMemorySize, SMEM_DYN);
        cudaFuncSetAttribute(gemm_f16_2t<0>, cudaFuncAttributeMaxDynamicSharedMemorySize, SMEM_DYN);
        cudaFuncSetAttribute(gemm_f16_2t<2>, cudaFuncAttributeMaxDynamicSharedMemorySize, SMEM_DYN);
        attr_done = true;
    }

    void *p_fah, *p_fal, *p_wdh, *p_wdl, *p_wch, *p_wcl, *p_wuh, *p_wul;
    void *p_fl, *p_ab, *p_loc;
    cudaGetSymbolAddress(&p_fah, g_fa_h);  cudaGetSymbolAddress(&p_fal, g_fa_l);
    cudaGetSymbolAddress(&p_wdh, g_wdT_h); cudaGetSymbolAddress(&p_wdl, g_wdT_l);
    cudaGetSymbolAddress(&p_wch, g_wcT_h); cudaGetSymbolAddress(&p_wcl, g_wcT_l);
    cudaGetSymbolAddress(&p_wuh, g_wuT_h); cudaGetSymbolAddress(&p_wul, g_wuT_l);
    cudaGetSymbolAddress(&p_fl,  g_fl);
    cudaGetSymbolAddress(&p_ab,  g_AB);
    cudaGetSymbolAddress(&p_loc, g_loc);

    // 1) prep + split + KNN
    prep_weights_kernel<<<(PP * DD + 255) / 256, 256>>>(
        W_down, W_edge, W_up, b_edge, gamma, beta, mean, var);
    split_features_kernel<<<(MM * DD / 4 + 255) / 256, 256>>>((const float4*)features);
    knn_kernel<<<dim3(NN / 64, BB), 64>>>(points);

    // 2) feats_low = relu(features @ W_down + b_down)  [M=16384, N=256, K=1024]
    gemm_bf16_3t<<<dim3(PP / 128, MM / 128), 256, SMEM_DYN>>>(
        (const __nv_bfloat16*)p_fah, (const __nv_bfloat16*)p_fal,
        (const __nv_bfloat16*)p_wdh, (const __nv_bfloat16*)p_wdl,
        DD, PP, (__half*)p_fl, b_down);

    // 3) AB = feats_low @ Wcomb                        [M, N=512, K=256]
    gemm_f16_2t<0><<<dim3(2 * PP / 128, MM / 128), 256, SMEM_DYN>>>(
        (const __half*)p_fl, (const __half*)p_wch, (const __half*)p_wcl,
        PP, 2 * PP, (__half*)p_ab, nullptr, nullptr, nullptr);

    // 4) gather + BN + relu + max over K -> local (fp16)
    edge_max_kernel<<<MM, 256>>>();

    // 5) out = features + local @ W_up + b_up          [M, N=1024, K=256]
    gemm_f16_2t<2><<<dim3(DD / 128, MM / 128), 256, SMEM_DYN>>>(
        (const __half*)p_loc, (const __half*)p_wuh, (const __half*)p_wul,
        PP, DD, nullptr, out, b_up, features);
}

// round 5
// speedup vs baseline: 2.6624x; 1.2682x over previous
#include <cuda_runtime.h>
#include <cuda_bf16.h>
#include <cuda_fp16.h>
#include <cstdint>
#include <cfloat>

#define BB   16
#define NN   1024
#define DD   1024
#define PP   256
#define KNB  16
#define MM   (BB * NN)     // 16384

// ===================== helpers ==============================================
__device__ __forceinline__ uint32_t smem_u32(const void* p) {
    uint32_t a;
    asm("{ .reg .u64 t; cvta.to.shared.u64 t, %1; cvt.u32.u64 %0, t; }" : "=r"(a) : "l"(p));
    return a;
}
__device__ __forceinline__ uint64_t cvta_g(const void* p) {
    uint64_t r; asm("cvta.to.global.u64 %0, %1;" : "=l"(r) : "l"(p)); return r;
}
#define SMEM_SWIZZLE_128B(off) ((off) ^ (((off) >> 3) & 0x70))

#define CP_ASYNC16(dst, src) \
    asm volatile("cp.async.cg.shared.global [%0], [%1], 16;" :: "r"(dst), "l"(src) : "memory")
#define CP_COMMIT() asm volatile("cp.async.commit_group;" ::: "memory")
#define CP_WAIT(n)  asm volatile("cp.async.wait_group %0;" :: "n"(n) : "memory")

#define LDSM_X4(r0, r1, r2, r3, addr) \
    asm volatile("ldmatrix.sync.aligned.m8n8.x4.shared.b16 {%0,%1,%2,%3}, [%4];" \
                 : "=r"(r0), "=r"(r1), "=r"(r2), "=r"(r3) : "r"(addr))

#define MMA_F16(d, a, b) \
    asm volatile("mma.sync.aligned.m16n8k16.row.col.f32.f16.f16.f32 " \
                 "{%0,%1,%2,%3}, {%4,%5,%6,%7}, {%8,%9}, {%0,%1,%2,%3};" \
                 : "+f"((d)[0]), "+f"((d)[1]), "+f"((d)[2]), "+f"((d)[3]) \
                 : "r"((a)[0]), "r"((a)[1]), "r"((a)[2]), "r"((a)[3]), \
                   "r"((b)[0]), "r"((b)[1]))

// ===================== scratch ==============================================
__device__ __half g_fa[(size_t)MM * DD];      // features fp16 [M][1024]
__device__ __half g_wdT_h[PP * DD];           // W_down^T hi/lo fp16 [256][1024]
__device__ __half g_wdT_l[PP * DD];
__device__ __half g_wcT_h[2 * PP * PP];       // Wcomb^T hi/lo fp16 [512][256]
__device__ __half g_wcT_l[2 * PP * PP];
__device__ __half g_wuT_h[DD * PP];           // W_up^T hi/lo fp16 [1024][256]
__device__ __half g_wuT_l[DD * PP];
__device__ __half g_fl[(size_t)MM * PP];      // feats_low fp16 [M][256]
__device__ __half g_AB[(size_t)MM * 2 * PP];  // fp16 [M][0:256]=A',[256:512]=Bv
__device__ __half g_loc[(size_t)MM * PP];     // local fp16 [M][256]
__device__ int    g_idx[MM * KNB];
__device__ float  g_s[PP];
__device__ float  g_t[PP];

__device__ __forceinline__ void split_hf(float v, __half& h, __half& l) {
    h = __float2half_rn(v);
    l = __float2half_rn(v - __half2float(h));
}

// ===================== prep kernels =========================================
__global__ void split_features_kernel(const float4* __restrict__ f) {
    int i = blockIdx.x * blockDim.x + threadIdx.x;
    if (i >= MM * DD / 4) return;
    float4 v = f[i];
    __half hh[4];
    hh[0] = __float2half_rn(v.x);
    hh[1] = __float2half_rn(v.y);
    hh[2] = __float2half_rn(v.z);
    hh[3] = __float2half_rn(v.w);
    *(uint2*)(g_fa + 4 * (size_t)i) = *(uint2*)hh;
}

__global__ void prep_weights_kernel(const float* __restrict__ W_down,
                                    const float* __restrict__ W_edge,
                                    const float* __restrict__ W_up,
                                    const float* __restrict__ b_edge,
                                    const float* __restrict__ gamma,
                                    const float* __restrict__ beta,
                                    const float* __restrict__ mean,
                                    const float* __restrict__ var) {
    int t = blockIdx.x * blockDim.x + threadIdx.x;
    if (t < PP * DD) {  // W_down^T fp16 hi/lo
        float v = W_down[(size_t)(t & 1023) * PP + (t >> 10)];
        split_hf(v, g_wdT_h[t], g_wdT_l[t]);
    }
    if (t < DD * PP) {  // W_up^T fp16 hi/lo
        float v = W_up[(size_t)(t & 255) * DD + (t >> 8)];
        split_hf(v, g_wuT_h[t], g_wuT_l[t]);
    }
    if (t < 2 * PP * PP) {  // Wcomb^T fp16 hi/lo
        int p = t >> 8, f = t & 255;
        float v = (p < PP) ? (W_edge[f * PP + p] - W_edge[(f + PP) * PP + p])
                           : W_edge[(f + PP) * PP + (p - PP)];
        split_hf(v, g_wcT_h[t], g_wcT_l[t]);
    }
    if (t < PP) {
        float rs = rsqrtf(var[t] + 1e-5f);
        float sv = gamma[t] * rs;
        g_s[t] = sv;
        g_t[t] = beta[t] - mean[t] * sv + sv * b_edge[t];
    }
}

// ===================== KNN: split candidates 2-way per point ================
// block = 256 threads: threads [0,128) = half 0, [128,256) = half 1.
// Each thread scans 512 candidates for its point; halves merged in smem.
__global__ __launch_bounds__(256) void knn_kernel(const float* __restrict__ pts) {
    const int b    = blockIdx.y;
    const int half = threadIdx.x >> 7;
    const int pl   = threadIdx.x & 127;
    const int n    = blockIdx.x * 128 + pl;

    __shared__ float4 sp[NN];          // 16 KB (x, y, z, |p|^2)
    __shared__ float  sd[128][17];
    __shared__ int    si[128][17];

    for (int m = threadIdx.x; m < NN; m += 256) {
        float x = pts[((size_t)b * NN + m) * 3 + 0];
        float y = pts[((size_t)b * NN + m) * 3 + 1];
        float z = pts[((size_t)b * NN + m) * 3 + 2];
        sp[m] = make_float4(x, y, z, fmaf(x, x, fmaf(y, y, z * z)));
    }
    __syncthreads();

    const float4 P = sp[n];

    float bd[KNB]; int bi[KNB];
#pragma unroll
    for (int j = 0; j < KNB; ++j) { bd[j] = FLT_MAX; bi[j] = 0; }

    const int m0 = half * 512;
    for (int mm = 0; mm < 512; ++mm) {
        const int m = m0 + mm;
        float4 q = sp[m];
        float dot = fmaf(P.x, q.x, fmaf(P.y, q.y, P.z * q.z));
        float d = P.w + q.w - 2.0f * dot;
        if (d < bd[KNB - 1]) {
            float dc = d; int ic = m;
#pragma unroll
            for (int j = 0; j < KNB; ++j) {
                if (dc < bd[j]) {
                    float td = bd[j]; bd[j] = dc; dc = td;
                    int   ti = bi[j]; bi[j] = ic; ic = ti;
                }
            }
        }
    }

    if (half == 1) {
#pragma unroll
        for (int j = 0; j < KNB; ++j) { sd[pl][j] = bd[j]; si[pl][j] = bi[j]; }
    }
    __syncthreads();

    if (half == 0) {
#pragma unroll
        for (int j = 0; j < KNB; ++j) {
            float dc = sd[pl][j]; int ic = si[pl][j];
            if (dc < bd[KNB - 1]) {
#pragma unroll
                for (int q = 0; q < KNB; ++q) {
                    if (dc < bd[q]) {
                        float td = bd[q]; bd[q] = dc; dc = td;
                        int   ti = bi[q]; bi[q] = ic; ic = ti;
                    }
                }
            }
        }
        int base = ((size_t)b * NN + n) * KNB;
#pragma unroll
        for (int j = 0; j < KNB; ++j) g_idx[base + j] = bi[j];
    }
}

// ===================== edge gather + BN + relu + max ========================
__global__ __launch_bounds__(256) void edge_max_kernel() {
    const int bn = blockIdx.x;
    const int p  = threadIdx.x;
    const int b  = bn >> 10;

    __shared__ int sidx[KNB];
    if (p < KNB) sidx[p] = g_idx[bn * KNB + p];
    __syncthreads();

    const float a  = __half2float(g_AB[(size_t)bn * 512 + p]);
    const float sp = g_s[p];
    const float tp = g_t[p];

    float acc = 0.0f;
#pragma unroll
    for (int k = 0; k < KNB; ++k) {
        float v = __half2float(g_AB[(size_t)((b << 10) + sidx[k]) * 512 + PP + p]);
        float h = fmaf(sp, a + v, tp);
        acc = fmaxf(acc, h);
    }
    g_loc[(size_t)bn * PP + p] = __float2half_rn(acc);
}

// ===================== GEMM fp16 2-term, 2-stage, k-chunk 64 ================
// C = A(fp16) @ (Bh+Bl)^T ; B stored [N][K].
// EPI 0: store fp16 ; EPI 1: relu(acc+bias) -> fp16 ; EPI 2: acc+bias+res -> f32.
template <int EPI>
__global__ void __launch_bounds__(256, 2) gemm_f16_2t(
    const __half* __restrict__ A,
    const __half* __restrict__ Bh, const __half* __restrict__ Bl,
    int K, int Nc,
    __half* __restrict__ Ch, float* __restrict__ Cf,
    const float* __restrict__ bias, const float* __restrict__ res)
{
    extern __shared__ char smraw[];
    const uint32_t smb = smem_u32(smraw);   // 2 buffers x 48KB: [A | Bh | Bl]
    const int tid = threadIdx.x, lane = tid & 31, wid = tid >> 5;
    const int warp_m = wid & 3, warp_n = wid >> 2;
    const int bm = blockIdx.y, bn = blockIdx.x;

    const uint64_t gA  = cvta_g(A  + (size_t)(bm * 128) * K);
    const uint64_t gBh = cvta_g(Bh + (size_t)(bn * 128) * K);
    const uint64_t gBl = cvta_g(Bl + (size_t)(bn * 128) * K);
    const int nk = K >> 6;

    const int grp = lane >> 3, rr = lane & 7;
    const int a_row0 = warp_m * 32 + ((grp & 1) << 3) + rr;
    const int kadd_a = (grp >> 1) << 4;
    const int b_row0 = warp_n * 64 + ((grp >> 1) << 3) + rr;
    const int kadd_b = (grp & 1) << 4;

    float acc[2][8][4];
#pragma unroll
    for (int i = 0; i < 2; ++i)
#pragma unroll
        for (int j = 0; j < 8; ++j)
#pragma unroll
            for (int c = 0; c < 4; ++c) acc[i][j][c] = 0.0f;

    auto issue = [&](int kc) {
        const uint32_t bb = (uint32_t)(kc & 1) * 49152u;
        const int kof = kc * 64;
#pragma unroll
        for (int i = 0; i < 4; ++i) {
            int idx = i * 256 + tid;
            int row = idx >> 3, g = idx & 7;
            int kel = kof + g * 8;
            uint32_t dst = SMEM_SWIZZLE_128B((uint32_t)(row * 128 + g * 16));
            size_t src = (size_t)row * K + kel;
            CP_ASYNC16(smb + bb + dst,         gA  + src * 2);
            CP_ASYNC16(smb + bb + 16384 + dst, gBh + src * 2);
            CP_ASYNC16(smb + bb + 32768 + dst, gBl + src * 2);
        }
    };

    issue(0); CP_COMMIT();

    for (int kc = 0; kc < nk; ++kc) {
        if (kc + 1 < nk) issue(kc + 1);
        CP_COMMIT();
        CP_WAIT(1);
        __syncthreads();

        const uint32_t bufA  = smb + (uint32_t)(kc & 1) * 49152u;
        const uint32_t bufBh = bufA + 16384;
        const uint32_t bufBl = bufA + 32768;

#pragma unroll
        for (int s = 0; s < 4; ++s) {
            uint32_t af[2][4];
#pragma unroll
            for (int mt = 0; mt < 2; ++mt) {
                int row = a_row0 + mt * 16;
                uint32_t rb = bufA + row * 128;
                uint32_t xr = (row & 7) << 4;
                LDSM_X4(af[mt][0], af[mt][1], af[mt][2], af[mt][3],
                        rb + (((uint32_t)(s * 32 + kadd_a)) ^ xr));
            }
#pragma unroll
            for (int jg = 0; jg < 2; ++jg) {
                uint32_t bh[4][2], bl[4][2];
#pragma unroll
                for (int p = 0; p < 2; ++p) {
                    int row = b_row0 + jg * 32 + p * 16;
                    uint32_t xr = (row & 7) << 4;
                    uint32_t by = (uint32_t)(s * 32 + kadd_b);
                    LDSM_X4(bh[2 * p][0], bh[2 * p][1], bh[2 * p + 1][0], bh[2 * p + 1][1],
                            bufBh + row * 128 + (by ^ xr));
                    LDSM_X4(bl[2 * p][0], bl[2 * p][1], bl[2 * p + 1][0], bl[2 * p + 1][1],
                            bufBl + row * 128 + (by ^ xr));
                }
#pragma unroll
                for (int mt = 0; mt < 2; ++mt)
#pragma unroll
                    for (int j = 0; j < 4; ++j) {
                        float* d = acc[mt][jg * 4 + j];
                        MMA_F16(d, af[mt], bh[j]);
                        MMA_F16(d, af[mt], bl[j]);
                    }
            }
        }
        __syncthreads();
    }

#pragma unroll
    for (int mt = 0; mt < 2; ++mt)
#pragma unroll
        for (int half = 0; half < 2; ++half) {
            size_t row = (size_t)bm * 128 + warp_m * 32 + mt * 16 + half * 8 + (lane >> 2);
#pragma unroll
            for (int j = 0; j < 8; ++j) {
                int col = bn * 128 + warp_n * 64 + j * 8 + 2 * (lane & 3);
                float v0 = acc[mt][j][half * 2 + 0];
                float v1 = acc[mt][j][half * 2 + 1];
                if (EPI == 0) {
                    __half2 hv; hv.x = __float2half_rn(v0); hv.y = __float2half_rn(v1);
                    *(__half2*)(Ch + row * Nc + col) = hv;
                } else if (EPI == 1) {
                    v0 = fmaxf(v0 + bias[col], 0.0f);
                    v1 = fmaxf(v1 + bias[col + 1], 0.0f);
                    __half2 hv; hv.x = __float2half_rn(v0); hv.y = __float2half_rn(v1);
                    *(__half2*)(Ch + row * Nc + col) = hv;
                } else {
                    float2 r = *(const float2*)(res + row * Nc + col);
                    *(float2*)(Cf + row * Nc + col) =
                        make_float2(v0 + bias[col] + r.x, v1 + bias[col + 1] + r.y);
                }
            }
        }
}

// ===================== launch ===============================================
extern "C" void kernel_launch(void* const* d_in, const int* in_sizes, int n_in,
                              void* d_out, int out_size)
{
    const float* points   = (const float*)d_in[0];
    const float* features = (const float*)d_in[1];
    const float* W_down   = (const float*)d_in[2];
    const float* b_down   = (const float*)d_in[3];
    const float* W_edge   = (const float*)d_in[4];
    const float* b_edge   = (const float*)d_in[5];
    const float* gamma    = (const float*)d_in[6];
    const float* beta     = (const float*)d_in[7];
    const float* mean     = (const float*)d_in[8];
    const float* var      = (const float*)d_in[9];
    const float* W_up     = (const float*)d_in[10];
    const float* b_up     = (const float*)d_in[11];
    float* out = (float*)d_out;

    const int SMEM_DYN = 98304;
    static bool attr_done = false;
    if (!attr_done) {
        cudaFuncSetAttribute(gemm_f16_2t<0>, cudaFuncAttributeMaxDynamicSharedMemorySize, SMEM_DYN);
        cudaFuncSetAttribute(gemm_f16_2t<1>, cudaFuncAttributeMaxDynamicSharedMemorySize, SMEM_DYN);
        cudaFuncSetAttribute(gemm_f16_2t<2>, cudaFuncAttributeMaxDynamicSharedMemorySize, SMEM_DYN);
        attr_done = true;
    }

    void *p_fa, *p_wdh, *p_wdl, *p_wch, *p_wcl, *p_wuh, *p_wul;
    void *p_fl, *p_ab, *p_loc;
    cudaGetSymbolAddress(&p_fa,  g_fa);
    cudaGetSymbolAddress(&p_wdh, g_wdT_h); cudaGetSymbolAddress(&p_wdl, g_wdT_l);
    cudaGetSymbolAddress(&p_wch, g_wcT_h); cudaGetSymbolAddress(&p_wcl, g_wcT_l);
    cudaGetSymbolAddress(&p_wuh, g_wuT_h); cudaGetSymbolAddress(&p_wul, g_wuT_l);
    cudaGetSymbolAddress(&p_fl,  g_fl);
    cudaGetSymbolAddress(&p_ab,  g_AB);
    cudaGetSymbolAddress(&p_loc, g_loc);

    // 1) prep + split + KNN
    prep_weights_kernel<<<(PP * DD + 255) / 256, 256>>>(
        W_down, W_edge, W_up, b_edge, gamma, beta, mean, var);
    split_features_kernel<<<(MM * DD / 4 + 255) / 256, 256>>>((const float4*)features);
    knn_kernel<<<dim3(NN / 128, BB), 256>>>(points);

    // 2) feats_low = relu(features @ W_down + b_down)  [M=16384, N=256, K=1024]
    gemm_f16_2t<1><<<dim3(PP / 128, MM / 128), 256, SMEM_DYN>>>(
        (const __half*)p_fa, (const __half*)p_wdh, (const __half*)p_wdl,
        DD, PP, (__half*)p_fl, nullptr, b_down, nullptr);

    // 3) AB = feats_low @ Wcomb                        [M, N=512, K=256]
    gemm_f16_2t<0><<<dim3(2 * PP / 128, MM / 128), 256, SMEM_DYN>>>(
        (const __half*)p_fl, (const __half*)p_wch, (const __half*)p_wcl,
        PP, 2 * PP, (__half*)p_ab, nullptr, nullptr, nullptr);

    // 4) gather + BN + relu + max over K -> local (fp16)
    edge_max_kernel<<<MM, 256>>>();

    // 5) out = features + local @ W_up + b_up          [M, N=1024, K=256]
    gemm_f16_2t<2><<<dim3(DD / 128, MM / 128), 256, SMEM_DYN>>>(
        (const __half*)p_loc, (const __half*)p_wuh, (const __half*)p_wul,
        PP, DD, nullptr, out, b_up, features);
}